// round 2
// baseline (speedup 1.0000x reference)
#include <cuda_runtime.h>

// Problem constants
#define T_TOK   512
#define H_DIM   2048
#define I_DIM   1024
#define N_EXP   16
#define K_TOP   4
#define N_PAIR  (T_TOK * K_TOP)   // 2048 token-expert pairs
#define QBS     128               // quant block size

// GEMM tiling
#define TM      128
#define TN      64
#define TKC     32
#define NTHR    256

// ---------------------------------------------------------------------------
// Scratch (device globals: no allocation allowed in kernel_launch)
// ---------------------------------------------------------------------------
__device__ int   g_off[N_EXP + 1];          // per-expert offsets into g_pair
__device__ int   g_pair[N_PAIR];            // pair ids (t*K_TOP + k) grouped by expert
__device__ __align__(16) float g_hact[(N_PAIR + TM) * I_DIM]; // silu(g)*u, grouped rows (+pad)

// ---------------------------------------------------------------------------
// Kernel 1: routing — bucket the 2048 (t,k) pairs by expert. Single block.
// Robust to selected_experts being int32 OR int64 (JAX x64-off silently
// downcasts jnp.int64 -> int32). Detection reads only the first 8KB, which
// is in-bounds for both layouts.
// ---------------------------------------------------------------------------
__global__ void route_kernel(const int* __restrict__ sel32)
{
    __shared__ int cnt[N_EXP];
    __shared__ int cur[N_EXP];
    __shared__ int is64;
    const int tid = threadIdx.x;

    if (tid == 0) is64 = 1;
    if (tid < N_EXP) cnt[tid] = 0;
    __syncthreads();

    // If truly int64 (little-endian, values in [0,16)), every odd 32-bit word
    // of the first N_PAIR words is a zero upper half. If int32, odd words are
    // random experts — all-zero has probability (1/16)^1024 ~ 0.
    for (int p = tid; p < N_PAIR / 2; p += NTHR)
        if (sel32[2 * p + 1] != 0) atomicExch(&is64, 0);
    __syncthreads();

    const int stride = is64 ? 2 : 1;

    for (int p = tid; p < N_PAIR; p += NTHR) {
        int e = sel32[(size_t)p * stride] & 15;   // clamp: crash guard
        atomicAdd(&cnt[e], 1);
    }
    __syncthreads();

    if (tid == 0) {
        int acc = 0;
        for (int e = 0; e < N_EXP; e++) {
            g_off[e] = acc;
            cur[e]   = acc;
            acc += cnt[e];
        }
        g_off[N_EXP] = acc;   // == N_PAIR
    }
    __syncthreads();

    for (int p = tid; p < N_PAIR; p += NTHR) {
        int e   = sel32[(size_t)p * stride] & 15;
        int pos = atomicAdd(&cur[e], 1);
        g_pair[pos] = p;
    }
}

// ---------------------------------------------------------------------------
// Kernel 2: fused up-projection. For each expert e and its assigned rows:
//   g[m,i] = sum_h x[t_m,h] * w0[e,i,h] * s0[e,i/128,h/128]
//   u[m,i] = sum_h x[t_m,h] * w1[e,i,h] * s1[e,i/128,h/128]
//   hact[m,i] = silu(g) * u            (written to grouped scratch)
// ---------------------------------------------------------------------------
__global__ __launch_bounds__(NTHR, 2)
void gemm1_kernel(const float* __restrict__ x,
                  const float* __restrict__ w0,
                  const float* __restrict__ w1,
                  const float* __restrict__ s0,
                  const float* __restrict__ s1)
{
    const int e    = blockIdx.y;
    const int base = g_off[e];
    const int cntE = g_off[e + 1] - base;
    const int m0   = blockIdx.z * TM;
    if (m0 >= cntE) return;
    const int n0   = blockIdx.x * TN;

    __shared__ float As [TKC][TM];
    __shared__ float B0s[TKC][TN];
    __shared__ float B1s[TKC][TN];
    __shared__ int   srow[TM];

    const int tid = threadIdx.x;
    const int tx  = tid & 15;   // n group: cols tx*4 .. tx*4+3
    const int ty  = tid >> 4;   // m group: rows ty*8 .. ty*8+7

    if (tid < TM) {
        int mm = m0 + tid;
        srow[tid] = (mm < cntE) ? (g_pair[base + mm] / K_TOP) : 0; // row 0 tail (never written)
    }
    __syncthreads();

    float acc_g[8][4];
    float acc_u[8][4];
    #pragma unroll
    for (int i = 0; i < 8; i++)
        #pragma unroll
        for (int j = 0; j < 4; j++) { acc_g[i][j] = 0.f; acc_u[i][j] = 0.f; }

    // loader lane assignments
    const int lm   = tid >> 1;            // x row 0..127 (2 threads/row)
    const int loff = (tid & 1) * 16;      // 16 consecutive h per thread
    const int ln   = tid >> 2;            // w row 0..63 (4 threads/row)
    const int lq   = (tid & 3) * 8;       // 8 consecutive h per thread

    const int iblk = n0 >> 7;             // i-quant-block (TN=64 never straddles)
    const float* xrow  = x  + (size_t)srow[lm] * H_DIM + loff;
    const float* w0row = w0 + ((size_t)(e * I_DIM + n0 + ln)) * H_DIM + lq;
    const float* w1row = w1 + ((size_t)(e * I_DIM + n0 + ln)) * H_DIM + lq;
    const float* s0p   = s0 + (e * (I_DIM / QBS) + iblk) * (H_DIM / QBS);
    const float* s1p   = s1 + (e * (I_DIM / QBS) + iblk) * (H_DIM / QBS);

    for (int kt = 0; kt < H_DIM / TKC; kt++) {
        // --- load x tile (gathered rows), store [k][m] transposed ---
        {
            const float* p = xrow + kt * TKC;
            #pragma unroll
            for (int q = 0; q < 4; q++) {
                float4 v = *(const float4*)(p + q * 4);
                As[loff + q * 4 + 0][lm] = v.x;
                As[loff + q * 4 + 1][lm] = v.y;
                As[loff + q * 4 + 2][lm] = v.z;
                As[loff + q * 4 + 3][lm] = v.w;
            }
        }
        // --- load w0/w1 tiles, dequant-scale applied at store ---
        {
            const float sc0 = s0p[kt >> 2];  // h-block = (kt*32)/128
            const float sc1 = s1p[kt >> 2];
            const float* p0 = w0row + kt * TKC;
            const float* p1 = w1row + kt * TKC;
            #pragma unroll
            for (int q = 0; q < 2; q++) {
                float4 v0 = *(const float4*)(p0 + q * 4);
                float4 v1 = *(const float4*)(p1 + q * 4);
                B0s[lq + q * 4 + 0][ln] = v0.x * sc0;
                B0s[lq + q * 4 + 1][ln] = v0.y * sc0;
                B0s[lq + q * 4 + 2][ln] = v0.z * sc0;
                B0s[lq + q * 4 + 3][ln] = v0.w * sc0;
                B1s[lq + q * 4 + 0][ln] = v1.x * sc1;
                B1s[lq + q * 4 + 1][ln] = v1.y * sc1;
                B1s[lq + q * 4 + 2][ln] = v1.z * sc1;
                B1s[lq + q * 4 + 3][ln] = v1.w * sc1;
            }
        }
        __syncthreads();

        #pragma unroll 8
        for (int kk = 0; kk < TKC; kk++) {
            float4 a0 = *(const float4*)&As [kk][ty * 8];
            float4 a1 = *(const float4*)&As [kk][ty * 8 + 4];
            float4 b0 = *(const float4*)&B0s[kk][tx * 4];
            float4 b1 = *(const float4*)&B1s[kk][tx * 4];
            float a[8] = {a0.x, a0.y, a0.z, a0.w, a1.x, a1.y, a1.z, a1.w};
            float bg[4] = {b0.x, b0.y, b0.z, b0.w};
            float bu[4] = {b1.x, b1.y, b1.z, b1.w};
            #pragma unroll
            for (int i = 0; i < 8; i++)
                #pragma unroll
                for (int j = 0; j < 4; j++) {
                    acc_g[i][j] = fmaf(a[i], bg[j], acc_g[i][j]);
                    acc_u[i][j] = fmaf(a[i], bu[j], acc_u[i][j]);
                }
        }
        __syncthreads();
    }

    // --- epilogue: hact = silu(g) * u ---
    #pragma unroll
    for (int i = 0; i < 8; i++) {
        int mm = m0 + ty * 8 + i;
        if (mm < cntE) {
            int grow = base + mm;
            float4 hv;
            #pragma unroll
            for (int j = 0; j < 4; j++) {
                float g = acc_g[i][j];
                float s = g / (1.0f + __expf(-g));   // silu
                ((float*)&hv)[j] = s * acc_u[i][j];
            }
            *(float4*)&g_hact[(size_t)grow * I_DIM + n0 + tx * 4] = hv;
        }
    }
}

// ---------------------------------------------------------------------------
// Kernel 3: down-projection + routing weight.
//   y[m,h] = sum_i hact[m,i] * w2[e,h,i] * s2[e,h/128,i/128]
//   out[pid,h] = y[m,h] * rw[pid]        (pid = t*K_TOP + k)
// ---------------------------------------------------------------------------
__global__ __launch_bounds__(NTHR, 2)
void gemm2_kernel(const float* __restrict__ w2,
                  const float* __restrict__ s2,
                  const float* __restrict__ rw,
                  float* __restrict__ out)
{
    const int e    = blockIdx.y;
    const int base = g_off[e];
    const int cntE = g_off[e + 1] - base;
    const int m0   = blockIdx.z * TM;
    if (m0 >= cntE) return;
    const int n0   = blockIdx.x * TN;   // over H

    __shared__ float As[TKC][TM];
    __shared__ float Bs[TKC][TN];
    __shared__ int   spair[TM];

    const int tid = threadIdx.x;
    const int tx  = tid & 15;
    const int ty  = tid >> 4;

    if (tid < TM) {
        int mm = m0 + tid;
        spair[tid] = (mm < cntE) ? g_pair[base + mm] : 0;
    }
    __syncthreads();

    float acc[8][4];
    #pragma unroll
    for (int i = 0; i < 8; i++)
        #pragma unroll
        for (int j = 0; j < 4; j++) acc[i][j] = 0.f;

    const int lm   = tid >> 1;
    const int loff = (tid & 1) * 16;
    const int ln   = tid >> 2;
    const int lq   = (tid & 3) * 8;

    const int hblk = n0 >> 7;
    const float* arow  = g_hact + (size_t)(base + m0 + lm) * I_DIM + loff; // contiguous grouped rows
    const float* w2row = w2 + ((size_t)(e * H_DIM + n0 + ln)) * I_DIM + lq;
    const float* s2p   = s2 + (e * (H_DIM / QBS) + hblk) * (I_DIM / QBS);

    for (int kt = 0; kt < I_DIM / TKC; kt++) {
        {
            const float* p = arow + kt * TKC;
            #pragma unroll
            for (int q = 0; q < 4; q++) {
                float4 v = *(const float4*)(p + q * 4);
                As[loff + q * 4 + 0][lm] = v.x;
                As[loff + q * 4 + 1][lm] = v.y;
                As[loff + q * 4 + 2][lm] = v.z;
                As[loff + q * 4 + 3][lm] = v.w;
            }
        }
        {
            const float sc = s2p[kt >> 2];
            const float* p = w2row + kt * TKC;
            #pragma unroll
            for (int q = 0; q < 2; q++) {
                float4 v = *(const float4*)(p + q * 4);
                Bs[lq + q * 4 + 0][ln] = v.x * sc;
                Bs[lq + q * 4 + 1][ln] = v.y * sc;
                Bs[lq + q * 4 + 2][ln] = v.z * sc;
                Bs[lq + q * 4 + 3][ln] = v.w * sc;
            }
        }
        __syncthreads();

        #pragma unroll 8
        for (int kk = 0; kk < TKC; kk++) {
            float4 a0 = *(const float4*)&As[kk][ty * 8];
            float4 a1 = *(const float4*)&As[kk][ty * 8 + 4];
            float4 b  = *(const float4*)&Bs[kk][tx * 4];
            float a[8] = {a0.x, a0.y, a0.z, a0.w, a1.x, a1.y, a1.z, a1.w};
            float bb[4] = {b.x, b.y, b.z, b.w};
            #pragma unroll
            for (int i = 0; i < 8; i++)
                #pragma unroll
                for (int j = 0; j < 4; j++)
                    acc[i][j] = fmaf(a[i], bb[j], acc[i][j]);
        }
        __syncthreads();
    }

    #pragma unroll
    for (int i = 0; i < 8; i++) {
        int mm = m0 + ty * 8 + i;
        if (mm < cntE) {
            int   pid = spair[ty * 8 + i];
            float wgt = rw[pid];
            float4 ov;
            ov.x = acc[i][0] * wgt;
            ov.y = acc[i][1] * wgt;
            ov.z = acc[i][2] * wgt;
            ov.w = acc[i][3] * wgt;
            *(float4*)&out[(size_t)pid * H_DIM + n0 + tx * 4] = ov;
        }
    }
}

// ---------------------------------------------------------------------------
// Launch
// ---------------------------------------------------------------------------
extern "C" void kernel_launch(void* const* d_in, const int* in_sizes, int n_in,
                              void* d_out, int out_size)
{
    const float* x   = (const float*)d_in[0];
    const float* w0  = (const float*)d_in[1];
    const float* w1  = (const float*)d_in[2];
    const float* w2  = (const float*)d_in[3];
    const float* s0  = (const float*)d_in[4];
    const float* s1  = (const float*)d_in[5];
    const float* s2  = (const float*)d_in[6];
    const int*   sel = (const int*)  d_in[7];   // int32 or int64 — detected on device
    const float* rw  = (const float*)d_in[8];
    float*       out = (float*)d_out;

    route_kernel<<<1, NTHR>>>(sel);

    dim3 g1(I_DIM / TN, N_EXP, N_PAIR / TM);   // 16 x 16 x 16 (most z-tiles early-exit)
    gemm1_kernel<<<g1, NTHR>>>(x, w0, w1, s0, s1);

    dim3 g2(H_DIM / TN, N_EXP, N_PAIR / TM);   // 32 x 16 x 16
    gemm2_kernel<<<g2, NTHR>>>(w2, s2, rw, out);
}

// round 4
// speedup vs baseline: 1.5645x; 1.5645x over previous
#include <cuda_runtime.h>
#include <cuda_bf16.h>
#include <cstdint>

// Problem constants
#define T_TOK   512
#define H_DIM   2048
#define I_DIM   1024
#define N_EXP   16
#define K_TOP   4
#define N_PAIR  (T_TOK * K_TOP)
#define QBS     128

#define CTA_M   128
#define CTA_N   128
#define KI      64        // fp32 K per iteration
#define NTHR    256

// SMEM block: [rows][64 bf16] = rows x 128B, hi & lo variants
#define ABLK    16384     // 128 x 128B
#define BBLK    16384     // 128 x 128B
#define BUF_BYTES  (2*ABLK + 2*BBLK)        // Ahi,Alo,Bhi,Blo = 64KB
#define SMEM_DYN   (2*BUF_BYTES + 256)      // double buffer + align slack

// ---------------------------------------------------------------------------
// Scratch
// ---------------------------------------------------------------------------
__device__ int   g_off[N_EXP + 1];
__device__ int   g_pair[N_PAIR];
__device__ __align__(16) float g_hact[(N_PAIR + CTA_M) * I_DIM];

// ---------------------------------------------------------------------------
// Helpers
// ---------------------------------------------------------------------------
__device__ __forceinline__ uint32_t smem_u32(const void* p) {
    uint32_t a;
    asm("{ .reg .u64 t; cvta.to.shared.u64 t, %1; cvt.u32.u64 %0, t; }" : "=r"(a) : "l"(p));
    return a;
}

__device__ __forceinline__ void ldsm_x4(uint32_t* r, uint32_t addr) {
    asm volatile("ldmatrix.sync.aligned.m8n8.x4.shared.b16 {%0,%1,%2,%3}, [%4];"
        : "=r"(r[0]), "=r"(r[1]), "=r"(r[2]), "=r"(r[3]) : "r"(addr));
}
__device__ __forceinline__ void ldsm_x2(uint32_t* r, uint32_t addr) {
    asm volatile("ldmatrix.sync.aligned.m8n8.x2.shared.b16 {%0,%1}, [%2];"
        : "=r"(r[0]), "=r"(r[1]) : "r"(addr));
}

__device__ __forceinline__ void mma16816(float* c, const uint32_t* a, const uint32_t* b) {
    asm volatile(
        "mma.sync.aligned.m16n8k16.row.col.f32.bf16.bf16.f32 "
        "{%0,%1,%2,%3}, {%4,%5,%6,%7}, {%8,%9}, {%0,%1,%2,%3};"
        : "+f"(c[0]), "+f"(c[1]), "+f"(c[2]), "+f"(c[3])
        : "r"(a[0]), "r"(a[1]), "r"(a[2]), "r"(a[3]), "r"(b[0]), "r"(b[1]));
}

__device__ __forceinline__ void sts8(uint32_t addr, uint32_t v0, uint32_t v1) {
    asm volatile("st.shared.v2.b32 [%0], {%1,%2};" :: "r"(addr), "r"(v0), "r"(v1) : "memory");
}

// convert fp32x4 -> bf16 hi/lo quads, store 8B to hi block + 8B to lo block.
// phys offset handles the 128B XOR swizzle (16B chunk ^ row&7).
__device__ __forceinline__ void cvt_store(float4 v, int rb, int k0,
                                          uint32_t baseHi, uint32_t baseLo) {
    uint32_t chunk = (uint32_t)(k0 >> 3);
    uint32_t phys  = (uint32_t)rb * 128u + ((chunk ^ ((uint32_t)rb & 7u)) << 4) + ((k0 & 4) << 1);
    __nv_bfloat162 h0 = __floats2bfloat162_rn(v.x, v.y);
    __nv_bfloat162 h1 = __floats2bfloat162_rn(v.z, v.w);
    float rx = v.x - __bfloat162float(h0.x);
    float ry = v.y - __bfloat162float(h0.y);
    float rz = v.z - __bfloat162float(h1.x);
    float rw = v.w - __bfloat162float(h1.y);
    __nv_bfloat162 l0 = __floats2bfloat162_rn(rx, ry);
    __nv_bfloat162 l1 = __floats2bfloat162_rn(rz, rw);
    sts8(baseHi + phys, *(uint32_t*)&h0, *(uint32_t*)&h1);
    sts8(baseLo + phys, *(uint32_t*)&l0, *(uint32_t*)&l1);
}

// ---------------------------------------------------------------------------
// Kernel 0: routing (robust to int32/int64 selected_experts)
// ---------------------------------------------------------------------------
__global__ void route_kernel(const int* __restrict__ sel32)
{
    __shared__ int cnt[N_EXP];
    __shared__ int cur[N_EXP];
    __shared__ int is64;
    const int tid = threadIdx.x;

    if (tid == 0) is64 = 1;
    if (tid < N_EXP) cnt[tid] = 0;
    __syncthreads();

    for (int p = tid; p < N_PAIR / 2; p += NTHR)
        if (sel32[2 * p + 1] != 0) atomicExch(&is64, 0);
    __syncthreads();

    const int stride = is64 ? 2 : 1;
    for (int p = tid; p < N_PAIR; p += NTHR)
        atomicAdd(&cnt[sel32[(size_t)p * stride] & 15], 1);
    __syncthreads();

    if (tid == 0) {
        int acc = 0;
        for (int e = 0; e < N_EXP; e++) { g_off[e] = acc; cur[e] = acc; acc += cnt[e]; }
        g_off[N_EXP] = acc;
    }
    __syncthreads();

    for (int p = tid; p < N_PAIR; p += NTHR) {
        int e = sel32[(size_t)p * stride] & 15;
        g_pair[atomicAdd(&cur[e], 1)] = p;
    }
}

// ---------------------------------------------------------------------------
// Kernel 1: up-projection (bf16-split mma.sync).
// CTA: 128 pair-rows x 128 B-rows, where B rows interleave w0/w1:
//   B row r -> (r&1 ? w1 : w0) row (i0 + r/2)
// so each thread's acc col pair (2j, 2j+1) = (g_i, u_i) for i = i0 + j.
// Epilogue: silu(g)*u -> g_hact (grouped rows).
// ---------------------------------------------------------------------------
__global__ __launch_bounds__(NTHR, 1)
void gemm1_kernel(const float* __restrict__ x,  const float* __restrict__ w0,
                  const float* __restrict__ w1, const float* __restrict__ s0,
                  const float* __restrict__ s1)
{
    const int e    = blockIdx.y;
    const int base = g_off[e];
    const int cntE = g_off[e + 1] - base;
    const int m0   = blockIdx.z * CTA_M;
    if (m0 >= cntE) return;
    const int i0   = blockIdx.x * 64;      // 64 i-values per CTA (interleaved g|u)

    extern __shared__ char dsm[];
    __shared__ int srow[CTA_M];
    const uint32_t sb = (smem_u32(dsm) + 127u) & ~127u;

    const int tid  = threadIdx.x;
    const int wid  = tid >> 5;
    const int lane = tid & 31;

    if (tid < CTA_M) {
        int mm = m0 + tid;
        srow[tid] = (mm < cntE) ? (g_pair[base + mm] / K_TOP) : 0;
    }
    __syncthreads();

    // loader mapping: 2 threads per row, 32 f32 each
    const int rb = tid >> 1;
    const int kh = (tid & 1) * 32;
    const float* aSrc = x + (size_t)srow[rb] * H_DIM + kh;
    const int irow = i0 + (rb >> 1);
    const float* bSrc = (rb & 1)
        ? w1 + ((size_t)(e * I_DIM + irow)) * H_DIM + kh
        : w0 + ((size_t)(e * I_DIM + irow)) * H_DIM + kh;
    const int iblk = i0 >> 7;
    const float* sRow = ((rb & 1) ? s1 : s0) + (size_t)(e * (I_DIM / QBS) + iblk) * (H_DIM / QBS);

    // compute mapping
    const int wm = wid & 1, wn = wid >> 1;
    const int mW = wm * 64, nW = wn * 32;
    const int arow = lane & 15;
    const int ahalf = lane >> 4;
    const int brow = lane & 7;
    const int bhalf = (lane >> 3) & 1;

    float acc[4][4][4];
    #pragma unroll
    for (int a = 0; a < 4; a++)
        #pragma unroll
        for (int b = 0; b < 4; b++)
            #pragma unroll
            for (int c = 0; c < 4; c++) acc[a][b][c] = 0.f;

    const int NIT = H_DIM / KI;   // 32
    float4 aReg[8], bReg[8];

    // prologue: load iter 0, store to buf 0
    {
        const float4* ap = (const float4*)aSrc;
        const float4* bp = (const float4*)bSrc;
        #pragma unroll
        for (int q = 0; q < 8; q++) { aReg[q] = ap[q]; bReg[q] = bp[q]; }
        const float sc = sRow[0];
        #pragma unroll
        for (int q = 0; q < 8; q++) {
            cvt_store(aReg[q], rb, kh + q * 4, sb, sb + ABLK);
            float4 vb = bReg[q];
            vb.x *= sc; vb.y *= sc; vb.z *= sc; vb.w *= sc;
            cvt_store(vb, rb, kh + q * 4, sb + 2 * ABLK, sb + 2 * ABLK + BBLK);
        }
    }
    __syncthreads();

    for (int it = 0; it < NIT; it++) {
        // prefetch next iteration's globals
        if (it + 1 < NIT) {
            const float4* ap = (const float4*)(aSrc + (it + 1) * KI);
            const float4* bp = (const float4*)(bSrc + (it + 1) * KI);
            #pragma unroll
            for (int q = 0; q < 8; q++) { aReg[q] = ap[q]; bReg[q] = bp[q]; }
        }

        // compute from buf (it&1)
        const uint32_t bufB = sb + (uint32_t)(it & 1) * BUF_BYTES;
        const uint32_t sbAhi = bufB, sbAlo = bufB + ABLK;
        const uint32_t sbBhi = bufB + 2 * ABLK, sbBlo = sbBhi + BBLK;

        #pragma unroll
        for (int ks = 0; ks < 4; ks++) {
            uint32_t aH[4][4], aL[4][4], bH[4][2], bL[4][2];
            #pragma unroll
            for (int mf = 0; mf < 4; mf++) {
                uint32_t row  = (uint32_t)(mW + mf * 16 + arow);
                uint32_t off  = row * 128u + ((((uint32_t)(ks * 2 + ahalf)) ^ (row & 7u)) << 4);
                ldsm_x4(aH[mf], sbAhi + off);
                ldsm_x4(aL[mf], sbAlo + off);
            }
            #pragma unroll
            for (int nf = 0; nf < 4; nf++) {
                uint32_t row = (uint32_t)(nW + nf * 8 + brow);
                uint32_t off = row * 128u + ((((uint32_t)(ks * 2 + bhalf)) ^ (row & 7u)) << 4);
                ldsm_x2(bH[nf], sbBhi + off);
                ldsm_x2(bL[nf], sbBlo + off);
            }
            #pragma unroll
            for (int mf = 0; mf < 4; mf++)
                #pragma unroll
                for (int nf = 0; nf < 4; nf++) {
                    mma16816(acc[mf][nf], aH[mf], bH[nf]);
                    mma16816(acc[mf][nf], aL[mf], bH[nf]);
                    mma16816(acc[mf][nf], aH[mf], bL[nf]);
                }
        }

        // store next iteration to other buffer
        if (it + 1 < NIT) {
            const uint32_t nb = sb + (uint32_t)((it + 1) & 1) * BUF_BYTES;
            const float sc = sRow[(it + 1) >> 1];
            #pragma unroll
            for (int q = 0; q < 8; q++) {
                cvt_store(aReg[q], rb, kh + q * 4, nb, nb + ABLK);
                float4 vb = bReg[q];
                vb.x *= sc; vb.y *= sc; vb.z *= sc; vb.w *= sc;
                cvt_store(vb, rb, kh + q * 4, nb + 2 * ABLK, nb + 2 * ABLK + BBLK);
            }
        }
        __syncthreads();
    }

    // epilogue: silu(g)*u, col pair (2j,2j+1) = (g,u) for i = i0 + j
    const int qrow = lane >> 2;
    const int qcol = lane & 3;
    #pragma unroll
    for (int mf = 0; mf < 4; mf++) {
        const int r0 = mW + mf * 16 + qrow;
        const int r1 = r0 + 8;
        #pragma unroll
        for (int nf = 0; nf < 4; nf++) {
            const int ii = i0 + wn * 16 + nf * 4 + qcol;
            float g0 = acc[mf][nf][0], u0 = acc[mf][nf][1];
            float g1 = acc[mf][nf][2], u1 = acc[mf][nf][3];
            if (m0 + r0 < cntE) {
                float s = g0 / (1.0f + __expf(-g0));
                g_hact[(size_t)(base + m0 + r0) * I_DIM + ii] = s * u0;
            }
            if (m0 + r1 < cntE) {
                float s = g1 / (1.0f + __expf(-g1));
                g_hact[(size_t)(base + m0 + r1) * I_DIM + ii] = s * u1;
            }
        }
    }
}

// ---------------------------------------------------------------------------
// Kernel 2: down-projection (bf16-split mma.sync) + routing weight scatter.
// CTA: 128 grouped hact rows x 128 H-cols.
// ---------------------------------------------------------------------------
__global__ __launch_bounds__(NTHR, 1)
void gemm2_kernel(const float* __restrict__ w2, const float* __restrict__ s2,
                  const float* __restrict__ rw, float* __restrict__ out)
{
    const int e    = blockIdx.y;
    const int base = g_off[e];
    const int cntE = g_off[e + 1] - base;
    const int m0   = blockIdx.z * CTA_M;
    if (m0 >= cntE) return;
    const int n0   = blockIdx.x * CTA_N;   // H-tile

    extern __shared__ char dsm[];
    __shared__ int spair[CTA_M];
    const uint32_t sb = (smem_u32(dsm) + 127u) & ~127u;

    const int tid  = threadIdx.x;
    const int wid  = tid >> 5;
    const int lane = tid & 31;

    if (tid < CTA_M) {
        int mm = m0 + tid;
        spair[tid] = (mm < cntE) ? g_pair[base + mm] : 0;
    }
    __syncthreads();

    const int rb = tid >> 1;
    const int kh = (tid & 1) * 32;
    const float* aSrc = g_hact + (size_t)(base + m0 + rb) * I_DIM + kh;
    const float* bSrc = w2 + ((size_t)(e * H_DIM + n0 + rb)) * I_DIM + kh;
    const float* sRow = s2 + (size_t)(e * (H_DIM / QBS) + (n0 >> 7)) * (I_DIM / QBS);

    const int wm = wid & 1, wn = wid >> 1;
    const int mW = wm * 64, nW = wn * 32;
    const int arow = lane & 15;
    const int ahalf = lane >> 4;
    const int brow = lane & 7;
    const int bhalf = (lane >> 3) & 1;

    float acc[4][4][4];
    #pragma unroll
    for (int a = 0; a < 4; a++)
        #pragma unroll
        for (int b = 0; b < 4; b++)
            #pragma unroll
            for (int c = 0; c < 4; c++) acc[a][b][c] = 0.f;

    const int NIT = I_DIM / KI;   // 16
    float4 aReg[8], bReg[8];

    {
        const float4* ap = (const float4*)aSrc;
        const float4* bp = (const float4*)bSrc;
        #pragma unroll
        for (int q = 0; q < 8; q++) { aReg[q] = ap[q]; bReg[q] = bp[q]; }
        const float sc = sRow[0];
        #pragma unroll
        for (int q = 0; q < 8; q++) {
            cvt_store(aReg[q], rb, kh + q * 4, sb, sb + ABLK);
            float4 vb = bReg[q];
            vb.x *= sc; vb.y *= sc; vb.z *= sc; vb.w *= sc;
            cvt_store(vb, rb, kh + q * 4, sb + 2 * ABLK, sb + 2 * ABLK + BBLK);
        }
    }
    __syncthreads();

    for (int it = 0; it < NIT; it++) {
        if (it + 1 < NIT) {
            const float4* ap = (const float4*)(aSrc + (it + 1) * KI);
            const float4* bp = (const float4*)(bSrc + (it + 1) * KI);
            #pragma unroll
            for (int q = 0; q < 8; q++) { aReg[q] = ap[q]; bReg[q] = bp[q]; }
        }

        const uint32_t bufB = sb + (uint32_t)(it & 1) * BUF_BYTES;
        const uint32_t sbAhi = bufB, sbAlo = bufB + ABLK;
        const uint32_t sbBhi = bufB + 2 * ABLK, sbBlo = sbBhi + BBLK;

        #pragma unroll
        for (int ks = 0; ks < 4; ks++) {
            uint32_t aH[4][4], aL[4][4], bH[4][2], bL[4][2];
            #pragma unroll
            for (int mf = 0; mf < 4; mf++) {
                uint32_t row  = (uint32_t)(mW + mf * 16 + arow);
                uint32_t off  = row * 128u + ((((uint32_t)(ks * 2 + ahalf)) ^ (row & 7u)) << 4);
                ldsm_x4(aH[mf], sbAhi + off);
                ldsm_x4(aL[mf], sbAlo + off);
            }
            #pragma unroll
            for (int nf = 0; nf < 4; nf++) {
                uint32_t row = (uint32_t)(nW + nf * 8 + brow);
                uint32_t off = row * 128u + ((((uint32_t)(ks * 2 + bhalf)) ^ (row & 7u)) << 4);
                ldsm_x2(bH[nf], sbBhi + off);
                ldsm_x2(bL[nf], sbBlo + off);
            }
            #pragma unroll
            for (int mf = 0; mf < 4; mf++)
                #pragma unroll
                for (int nf = 0; nf < 4; nf++) {
                    mma16816(acc[mf][nf], aH[mf], bH[nf]);
                    mma16816(acc[mf][nf], aL[mf], bH[nf]);
                    mma16816(acc[mf][nf], aH[mf], bL[nf]);
                }
        }

        if (it + 1 < NIT) {
            const uint32_t nb = sb + (uint32_t)((it + 1) & 1) * BUF_BYTES;
            const float sc = sRow[(it + 1) >> 1];
            #pragma unroll
            for (int q = 0; q < 8; q++) {
                cvt_store(aReg[q], rb, kh + q * 4, nb, nb + ABLK);
                float4 vb = bReg[q];
                vb.x *= sc; vb.y *= sc; vb.z *= sc; vb.w *= sc;
                cvt_store(vb, rb, kh + q * 4, nb + 2 * ABLK, nb + 2 * ABLK + BBLK);
            }
        }
        __syncthreads();
    }

    // epilogue: scale by routing weight, scatter to out[pid]
    const int qrow = lane >> 2;
    const int qcol = lane & 3;
    #pragma unroll
    for (int mf = 0; mf < 4; mf++) {
        const int r0 = mW + mf * 16 + qrow;
        const int r1 = r0 + 8;
        const int pid0 = spair[r0];
        const int pid1 = spair[r1];
        const float w0g = rw[pid0];
        const float w1g = rw[pid1];
        #pragma unroll
        for (int nf = 0; nf < 4; nf++) {
            const int col = n0 + nW + nf * 8 + qcol * 2;
            if (m0 + r0 < cntE) {
                float2 v = { acc[mf][nf][0] * w0g, acc[mf][nf][1] * w0g };
                *(float2*)&out[(size_t)pid0 * H_DIM + col] = v;
            }
            if (m0 + r1 < cntE) {
                float2 v = { acc[mf][nf][2] * w1g, acc[mf][nf][3] * w1g };
                *(float2*)&out[(size_t)pid1 * H_DIM + col] = v;
            }
        }
    }
}

// ---------------------------------------------------------------------------
// Launch
// ---------------------------------------------------------------------------
extern "C" void kernel_launch(void* const* d_in, const int* in_sizes, int n_in,
                              void* d_out, int out_size)
{
    const float* x   = (const float*)d_in[0];
    const float* w0  = (const float*)d_in[1];
    const float* w1  = (const float*)d_in[2];
    const float* w2  = (const float*)d_in[3];
    const float* s0  = (const float*)d_in[4];
    const float* s1  = (const float*)d_in[5];
    const float* s2  = (const float*)d_in[6];
    const int*   sel = (const int*)  d_in[7];
    const float* rw  = (const float*)d_in[8];
    float*       out = (float*)d_out;

    cudaFuncSetAttribute(gemm1_kernel, cudaFuncAttributeMaxDynamicSharedMemorySize, SMEM_DYN);
    cudaFuncSetAttribute(gemm2_kernel, cudaFuncAttributeMaxDynamicSharedMemorySize, SMEM_DYN);

    route_kernel<<<1, NTHR>>>(sel);

    dim3 g1(I_DIM / 64, N_EXP, N_PAIR / CTA_M);    // 16 x 16 x 16 (z early-exits)
    gemm1_kernel<<<g1, NTHR, SMEM_DYN>>>(x, w0, w1, s0, s1);

    dim3 g2(H_DIM / CTA_N, N_EXP, N_PAIR / CTA_M); // 16 x 16 x 16
    gemm2_kernel<<<g2, NTHR, SMEM_DYN>>>(w2, s2, rw, out);
}

// round 6
// speedup vs baseline: 1.5865x; 1.0140x over previous
#include <cuda_runtime.h>
#include <cuda_bf16.h>
#include <cstdint>

// Problem constants
#define T_TOK   512
#define H_DIM   2048
#define I_DIM   1024
#define N_EXP   16
#define K_TOP   4
#define N_PAIR  (T_TOK * K_TOP)
#define QBS     128

#define CTA_M   128
#define CTA_N   64
#define KI      64        // fp32 K per iteration
#define NTHR    256

// SMEM blocks: rows x 128B (KI=64 bf16). A:128 rows, B:64 rows. hi+lo each.
#define ABLK    16384     // 128 x 128B
#define BBLK    8192      // 64 x 128B
#define BUF_BYTES  (2*ABLK + 2*BBLK)        // 48KB
#define SMEM_DYN   (2*BUF_BYTES + 256)      // double buffer -> ~96.25KB

// ---------------------------------------------------------------------------
// Scratch
// ---------------------------------------------------------------------------
__device__ int   g_off[N_EXP + 1];
__device__ int   g_pair[N_PAIR];
__device__ __align__(16) float g_hact[(N_PAIR + CTA_M) * I_DIM];

// ---------------------------------------------------------------------------
// Helpers
// ---------------------------------------------------------------------------
__device__ __forceinline__ uint32_t smem_u32(const void* p) {
    uint32_t a;
    asm("{ .reg .u64 t; cvta.to.shared.u64 t, %1; cvt.u32.u64 %0, t; }" : "=r"(a) : "l"(p));
    return a;
}

__device__ __forceinline__ void ldsm_x4(uint32_t* r, uint32_t addr) {
    asm volatile("ldmatrix.sync.aligned.m8n8.x4.shared.b16 {%0,%1,%2,%3}, [%4];"
        : "=r"(r[0]), "=r"(r[1]), "=r"(r[2]), "=r"(r[3]) : "r"(addr));
}
__device__ __forceinline__ void ldsm_x2(uint32_t* r, uint32_t addr) {
    asm volatile("ldmatrix.sync.aligned.m8n8.x2.shared.b16 {%0,%1}, [%2];"
        : "=r"(r[0]), "=r"(r[1]) : "r"(addr));
}

__device__ __forceinline__ void mma16816(float* c, const uint32_t* a, const uint32_t* b) {
    asm volatile(
        "mma.sync.aligned.m16n8k16.row.col.f32.bf16.bf16.f32 "
        "{%0,%1,%2,%3}, {%4,%5,%6,%7}, {%8,%9}, {%0,%1,%2,%3};"
        : "+f"(c[0]), "+f"(c[1]), "+f"(c[2]), "+f"(c[3])
        : "r"(a[0]), "r"(a[1]), "r"(a[2]), "r"(a[3]), "r"(b[0]), "r"(b[1]));
}

__device__ __forceinline__ void sts8(uint32_t addr, uint32_t v0, uint32_t v1) {
    asm volatile("st.shared.v2.b32 [%0], {%1,%2};" :: "r"(addr), "r"(v0), "r"(v1) : "memory");
}

// fp32x4 -> bf16 hi/lo, 8B to hi block + 8B to lo block; 128B-row XOR swizzle.
__device__ __forceinline__ void cvt_store(float4 v, int rb, int k0,
                                          uint32_t baseHi, uint32_t baseLo) {
    uint32_t chunk = (uint32_t)(k0 >> 3);
    uint32_t phys  = (uint32_t)rb * 128u + ((chunk ^ ((uint32_t)rb & 7u)) << 4) + ((k0 & 4) << 1);
    __nv_bfloat162 h0 = __floats2bfloat162_rn(v.x, v.y);
    __nv_bfloat162 h1 = __floats2bfloat162_rn(v.z, v.w);
    float rx = v.x - __bfloat162float(h0.x);
    float ry = v.y - __bfloat162float(h0.y);
    float rz = v.z - __bfloat162float(h1.x);
    float rw = v.w - __bfloat162float(h1.y);
    __nv_bfloat162 l0 = __floats2bfloat162_rn(rx, ry);
    __nv_bfloat162 l1 = __floats2bfloat162_rn(rz, rw);
    sts8(baseHi + phys, *(uint32_t*)&h0, *(uint32_t*)&h1);
    sts8(baseLo + phys, *(uint32_t*)&l0, *(uint32_t*)&l1);
}

// ---------------------------------------------------------------------------
// Kernel 0: routing (robust to int32/int64 selected_experts)
// ---------------------------------------------------------------------------
__global__ void route_kernel(const int* __restrict__ sel32)
{
    __shared__ int cnt[N_EXP];
    __shared__ int cur[N_EXP];
    __shared__ int is64;
    const int tid = threadIdx.x;

    if (tid == 0) is64 = 1;
    if (tid < N_EXP) cnt[tid] = 0;
    __syncthreads();

    for (int p = tid; p < N_PAIR / 2; p += NTHR)
        if (sel32[2 * p + 1] != 0) atomicExch(&is64, 0);
    __syncthreads();

    const int stride = is64 ? 2 : 1;
    for (int p = tid; p < N_PAIR; p += NTHR)
        atomicAdd(&cnt[sel32[(size_t)p * stride] & 15], 1);
    __syncthreads();

    if (tid == 0) {
        int acc = 0;
        for (int e = 0; e < N_EXP; e++) { g_off[e] = acc; cur[e] = acc; acc += cnt[e]; }
        g_off[N_EXP] = acc;
    }
    __syncthreads();

    for (int p = tid; p < N_PAIR; p += NTHR) {
        int e = sel32[(size_t)p * stride] & 15;
        g_pair[atomicAdd(&cur[e], 1)] = p;
    }
}

// ---------------------------------------------------------------------------
// Kernel 1: up-projection (bf16-split mma.sync). CTA 128 x 64.
// B rows interleave w0/w1: row r -> (r&1 ? w1 : w0) row (i0 + r/2);
// acc col pair (2j,2j+1) = (g_i, u_i). Epilogue: silu(g)*u -> g_hact.
// ---------------------------------------------------------------------------
__global__ __launch_bounds__(NTHR, 2)
void gemm1_kernel(const float* __restrict__ x,  const float* __restrict__ w0,
                  const float* __restrict__ w1, const float* __restrict__ s0,
                  const float* __restrict__ s1)
{
    const int e    = blockIdx.y;
    const int base = g_off[e];
    const int cntE = g_off[e + 1] - base;
    const int m0   = blockIdx.z * CTA_M;
    if (m0 >= cntE) return;
    const int i0   = blockIdx.x * 32;      // 32 i per CTA (64 interleaved rows)

    extern __shared__ char dsm[];
    __shared__ int srow[CTA_M];
    const uint32_t sb = (smem_u32(dsm) + 127u) & ~127u;

    const int tid  = threadIdx.x;
    const int wid  = tid >> 5;
    const int lane = tid & 31;

    if (tid < CTA_M) {
        int mm = m0 + tid;
        srow[tid] = (mm < cntE) ? (g_pair[base + mm] / K_TOP) : 0;
    }
    __syncthreads();

    // A loader: 2 threads/row, 32 f32 each
    const int rbA = tid >> 1;
    const int khA = (tid & 1) * 32;
    const float* aSrc = x + (size_t)srow[rbA] * H_DIM + khA;
    // B loader: 4 threads/row, 16 f32 each
    const int rbB = tid >> 2;
    const int khB = (tid & 3) * 16;
    const int irow = i0 + (rbB >> 1);
    const float* bSrc = (rbB & 1)
        ? w1 + ((size_t)(e * I_DIM + irow)) * H_DIM + khB
        : w0 + ((size_t)(e * I_DIM + irow)) * H_DIM + khB;
    const float* sRow = ((rbB & 1) ? s1 : s0)
        + (size_t)(e * (I_DIM / QBS) + (i0 >> 7)) * (H_DIM / QBS);

    // compute mapping: 4 M-warps x 2 N-warps
    const int wm = wid & 3, wn = wid >> 2;
    const int mW = wm * 32, nW = wn * 32;
    const int arow = lane & 15;
    const int ahalf = lane >> 4;
    const int brow = lane & 7;
    const int bhalf = (lane >> 3) & 1;

    float acc[2][4][4];
    #pragma unroll
    for (int a = 0; a < 2; a++)
        #pragma unroll
        for (int b = 0; b < 4; b++)
            #pragma unroll
            for (int c = 0; c < 4; c++) acc[a][b][c] = 0.f;

    const int NIT = H_DIM / KI;   // 32
    float4 aReg[8], bReg[4];

    // prologue: iter 0 -> buf 0
    {
        const float4* ap = (const float4*)aSrc;
        const float4* bp = (const float4*)bSrc;
        #pragma unroll
        for (int q = 0; q < 8; q++) aReg[q] = ap[q];
        #pragma unroll
        for (int q = 0; q < 4; q++) bReg[q] = bp[q];
        const float sc = sRow[0];
        #pragma unroll
        for (int q = 0; q < 8; q++)
            cvt_store(aReg[q], rbA, khA + q * 4, sb, sb + ABLK);
        #pragma unroll
        for (int q = 0; q < 4; q++) {
            float4 vb = bReg[q];
            vb.x *= sc; vb.y *= sc; vb.z *= sc; vb.w *= sc;
            cvt_store(vb, rbB, khB + q * 4, sb + 2 * ABLK, sb + 2 * ABLK + BBLK);
        }
    }
    __syncthreads();

    for (int it = 0; it < NIT; it++) {
        if (it + 1 < NIT) {
            const float4* ap = (const float4*)(aSrc + (it + 1) * KI);
            const float4* bp = (const float4*)(bSrc + (it + 1) * KI);
            #pragma unroll
            for (int q = 0; q < 8; q++) aReg[q] = ap[q];
            #pragma unroll
            for (int q = 0; q < 4; q++) bReg[q] = bp[q];
        }

        const uint32_t bufB = sb + (uint32_t)(it & 1) * BUF_BYTES;
        const uint32_t sbAhi = bufB, sbAlo = bufB + ABLK;
        const uint32_t sbBhi = bufB + 2 * ABLK, sbBlo = sbBhi + BBLK;

        #pragma unroll
        for (int ks = 0; ks < 4; ks++) {
            uint32_t aH[2][4], aL[2][4], bH[4][2], bL[4][2];
            #pragma unroll
            for (int mf = 0; mf < 2; mf++) {
                uint32_t row = (uint32_t)(mW + mf * 16 + arow);
                uint32_t off = row * 128u + ((((uint32_t)(ks * 2 + ahalf)) ^ (row & 7u)) << 4);
                ldsm_x4(aH[mf], sbAhi + off);
                ldsm_x4(aL[mf], sbAlo + off);
            }
            #pragma unroll
            for (int nf = 0; nf < 4; nf++) {
                uint32_t row = (uint32_t)(nW + nf * 8 + brow);
                uint32_t off = row * 128u + ((((uint32_t)(ks * 2 + bhalf)) ^ (row & 7u)) << 4);
                ldsm_x2(bH[nf], sbBhi + off);
                ldsm_x2(bL[nf], sbBlo + off);
            }
            #pragma unroll
            for (int mf = 0; mf < 2; mf++)
                #pragma unroll
                for (int nf = 0; nf < 4; nf++) {
                    mma16816(acc[mf][nf], aH[mf], bH[nf]);
                    mma16816(acc[mf][nf], aL[mf], bH[nf]);
                    mma16816(acc[mf][nf], aH[mf], bL[nf]);
                }
        }

        if (it + 1 < NIT) {
            const uint32_t nb = sb + (uint32_t)((it + 1) & 1) * BUF_BYTES;
            const float sc = sRow[(it + 1) >> 1];
            #pragma unroll
            for (int q = 0; q < 8; q++)
                cvt_store(aReg[q], rbA, khA + q * 4, nb, nb + ABLK);
            #pragma unroll
            for (int q = 0; q < 4; q++) {
                float4 vb = bReg[q];
                vb.x *= sc; vb.y *= sc; vb.z *= sc; vb.w *= sc;
                cvt_store(vb, rbB, khB + q * 4, nb + 2 * ABLK, nb + 2 * ABLK + BBLK);
            }
        }
        __syncthreads();
    }

    // epilogue: silu(g)*u, col pair (2j,2j+1) = (g,u) for i = i0 + wn*16 + nf*4 + qcol
    const int qrow = lane >> 2;
    const int qcol = lane & 3;
    #pragma unroll
    for (int mf = 0; mf < 2; mf++) {
        const int r0 = mW + mf * 16 + qrow;
        const int r1 = r0 + 8;
        #pragma unroll
        for (int nf = 0; nf < 4; nf++) {
            const int ii = i0 + wn * 16 + nf * 4 + qcol;
            float g0 = acc[mf][nf][0], u0 = acc[mf][nf][1];
            float g1 = acc[mf][nf][2], u1 = acc[mf][nf][3];
            if (m0 + r0 < cntE) {
                float s = g0 / (1.0f + __expf(-g0));
                g_hact[(size_t)(base + m0 + r0) * I_DIM + ii] = s * u0;
            }
            if (m0 + r1 < cntE) {
                float s = g1 / (1.0f + __expf(-g1));
                g_hact[(size_t)(base + m0 + r1) * I_DIM + ii] = s * u1;
            }
        }
    }
}

// ---------------------------------------------------------------------------
// Kernel 2: down-projection (bf16-split mma.sync) + routing weight scatter.
// CTA 128 x 64 H-cols.
// ---------------------------------------------------------------------------
__global__ __launch_bounds__(NTHR, 2)
void gemm2_kernel(const float* __restrict__ w2, const float* __restrict__ s2,
                  const float* __restrict__ rw, float* __restrict__ out)
{
    const int e    = blockIdx.y;
    const int base = g_off[e];
    const int cntE = g_off[e + 1] - base;
    const int m0   = blockIdx.z * CTA_M;
    if (m0 >= cntE) return;
    const int n0   = blockIdx.x * CTA_N;

    extern __shared__ char dsm[];
    __shared__ int spair[CTA_M];
    const uint32_t sb = (smem_u32(dsm) + 127u) & ~127u;

    const int tid  = threadIdx.x;
    const int wid  = tid >> 5;
    const int lane = tid & 31;

    if (tid < CTA_M) {
        int mm = m0 + tid;
        spair[tid] = (mm < cntE) ? g_pair[base + mm] : 0;
    }
    __syncthreads();

    const int rbA = tid >> 1;
    const int khA = (tid & 1) * 32;
    const float* aSrc = g_hact + (size_t)(base + m0 + rbA) * I_DIM + khA;
    const int rbB = tid >> 2;
    const int khB = (tid & 3) * 16;
    const float* bSrc = w2 + ((size_t)(e * H_DIM + n0 + rbB)) * I_DIM + khB;
    const float* sRow = s2 + (size_t)(e * (H_DIM / QBS) + (n0 >> 7)) * (I_DIM / QBS);

    const int wm = wid & 3, wn = wid >> 2;
    const int mW = wm * 32, nW = wn * 32;
    const int arow = lane & 15;
    const int ahalf = lane >> 4;
    const int brow = lane & 7;
    const int bhalf = (lane >> 3) & 1;

    float acc[2][4][4];
    #pragma unroll
    for (int a = 0; a < 2; a++)
        #pragma unroll
        for (int b = 0; b < 4; b++)
            #pragma unroll
            for (int c = 0; c < 4; c++) acc[a][b][c] = 0.f;

    const int NIT = I_DIM / KI;   // 16
    float4 aReg[8], bReg[4];

    {
        const float4* ap = (const float4*)aSrc;
        const float4* bp = (const float4*)bSrc;
        #pragma unroll
        for (int q = 0; q < 8; q++) aReg[q] = ap[q];
        #pragma unroll
        for (int q = 0; q < 4; q++) bReg[q] = bp[q];
        const float sc = sRow[0];
        #pragma unroll
        for (int q = 0; q < 8; q++)
            cvt_store(aReg[q], rbA, khA + q * 4, sb, sb + ABLK);
        #pragma unroll
        for (int q = 0; q < 4; q++) {
            float4 vb = bReg[q];
            vb.x *= sc; vb.y *= sc; vb.z *= sc; vb.w *= sc;
            cvt_store(vb, rbB, khB + q * 4, sb + 2 * ABLK, sb + 2 * ABLK + BBLK);
        }
    }
    __syncthreads();

    for (int it = 0; it < NIT; it++) {
        if (it + 1 < NIT) {
            const float4* ap = (const float4*)(aSrc + (it + 1) * KI);
            const float4* bp = (const float4*)(bSrc + (it + 1) * KI);
            #pragma unroll
            for (int q = 0; q < 8; q++) aReg[q] = ap[q];
            #pragma unroll
            for (int q = 0; q < 4; q++) bReg[q] = bp[q];
        }

        const uint32_t bufB = sb + (uint32_t)(it & 1) * BUF_BYTES;
        const uint32_t sbAhi = bufB, sbAlo = bufB + ABLK;
        const uint32_t sbBhi = bufB + 2 * ABLK, sbBlo = sbBhi + BBLK;

        #pragma unroll
        for (int ks = 0; ks < 4; ks++) {
            uint32_t aH[2][4], aL[2][4], bH[4][2], bL[4][2];
            #pragma unroll
            for (int mf = 0; mf < 2; mf++) {
                uint32_t row = (uint32_t)(mW + mf * 16 + arow);
                uint32_t off = row * 128u + ((((uint32_t)(ks * 2 + ahalf)) ^ (row & 7u)) << 4);
                ldsm_x4(aH[mf], sbAhi + off);
                ldsm_x4(aL[mf], sbAlo + off);
            }
            #pragma unroll
            for (int nf = 0; nf < 4; nf++) {
                uint32_t row = (uint32_t)(nW + nf * 8 + brow);
                uint32_t off = row * 128u + ((((uint32_t)(ks * 2 + bhalf)) ^ (row & 7u)) << 4);
                ldsm_x2(bH[nf], sbBhi + off);
                ldsm_x2(bL[nf], sbBlo + off);
            }
            #pragma unroll
            for (int mf = 0; mf < 2; mf++)
                #pragma unroll
                for (int nf = 0; nf < 4; nf++) {
                    mma16816(acc[mf][nf], aH[mf], bH[nf]);
                    mma16816(acc[mf][nf], aL[mf], bH[nf]);
                    mma16816(acc[mf][nf], aH[mf], bL[nf]);
                }
        }

        if (it + 1 < NIT) {
            const uint32_t nb = sb + (uint32_t)((it + 1) & 1) * BUF_BYTES;
            const float sc = sRow[(it + 1) >> 1];
            #pragma unroll
            for (int q = 0; q < 8; q++)
                cvt_store(aReg[q], rbA, khA + q * 4, nb, nb + ABLK);
            #pragma unroll
            for (int q = 0; q < 4; q++) {
                float4 vb = bReg[q];
                vb.x *= sc; vb.y *= sc; vb.z *= sc; vb.w *= sc;
                cvt_store(vb, rbB, khB + q * 4, nb + 2 * ABLK, nb + 2 * ABLK + BBLK);
            }
        }
        __syncthreads();
    }

    // epilogue: routing weight, scatter
    const int qrow = lane >> 2;
    const int qcol = lane & 3;
    #pragma unroll
    for (int mf = 0; mf < 2; mf++) {
        const int r0 = mW + mf * 16 + qrow;
        const int r1 = r0 + 8;
        const int pid0 = spair[r0];
        const int pid1 = spair[r1];
        const float w0g = rw[pid0];
        const float w1g = rw[pid1];
        #pragma unroll
        for (int nf = 0; nf < 4; nf++) {
            const int col = n0 + nW + nf * 8 + qcol * 2;
            if (m0 + r0 < cntE) {
                float2 v = { acc[mf][nf][0] * w0g, acc[mf][nf][1] * w0g };
                *(float2*)&out[(size_t)pid0 * H_DIM + col] = v;
            }
            if (m0 + r1 < cntE) {
                float2 v = { acc[mf][nf][2] * w1g, acc[mf][nf][3] * w1g };
                *(float2*)&out[(size_t)pid1 * H_DIM + col] = v;
            }
        }
    }
}

// ---------------------------------------------------------------------------
// Launch
// ---------------------------------------------------------------------------
extern "C" void kernel_launch(void* const* d_in, const int* in_sizes, int n_in,
                              void* d_out, int out_size)
{
    const float* x   = (const float*)d_in[0];
    const float* w0  = (const float*)d_in[1];
    const float* w1  = (const float*)d_in[2];
    const float* w2  = (const float*)d_in[3];
    const float* s0  = (const float*)d_in[4];
    const float* s1  = (const float*)d_in[5];
    const float* s2  = (const float*)d_in[6];
    const int*   sel = (const int*)  d_in[7];
    const float* rw  = (const float*)d_in[8];
    float*       out = (float*)d_out;

    cudaFuncSetAttribute(gemm1_kernel, cudaFuncAttributeMaxDynamicSharedMemorySize, SMEM_DYN);
    cudaFuncSetAttribute(gemm2_kernel, cudaFuncAttributeMaxDynamicSharedMemorySize, SMEM_DYN);

    route_kernel<<<1, NTHR>>>(sel);

    dim3 g1(I_DIM / 32, N_EXP, N_PAIR / CTA_M);    // 32 x 16 x 16 (z early-exits)
    gemm1_kernel<<<g1, NTHR, SMEM_DYN>>>(x, w0, w1, s0, s1);

    dim3 g2(H_DIM / CTA_N, N_EXP, N_PAIR / CTA_M); // 32 x 16 x 16
    gemm2_kernel<<<g2, NTHR, SMEM_DYN>>>(w2, s2, rw, out);
}